// round 15
// baseline (speedup 1.0000x reference)
#include <cuda_runtime.h>
#include <cuda_bf16.h>
#include <stdint.h>

#define B_  8
#define C_  512
#define L_  1024
#define BCL (B_*C_*L_)               // 4194304
#define ATT (64*1024*1024)

typedef unsigned short u16;
typedef unsigned int   u32;

// Scratch (device globals; allocation-free per harness rules)
__device__ __align__(16) u16 g_xnt_h[BCL];  // xn split-hi, [b][l][c]
__device__ __align__(16) u16 g_xnt_l[BCL];
__device__ __align__(16) u16 g_wh[4*C_*C_];
__device__ __align__(16) u16 g_wl[4*C_*C_];
__device__ __align__(16) u16 g_qh[BCL], g_ql[BCL];   // [bh][t][d] (scaled)
__device__ __align__(16) u16 g_kh[BCL], g_kl[BCL];   // [bh][s][d] (scaled)
__device__ __align__(16) u16 g_vh[BCL];              // [bh][d][s] (bf16 only)
__device__ __align__(16) u16 g_ah[BCL], g_al[BCL];   // [b][t][inner]
__device__ __align__(16) float g_attn_sink[ATT];

// ---------------------------------------------------------------------------
__device__ __forceinline__ void split1(float x, u16& h, u16& l) {
    __nv_bfloat16 hb = __float2bfloat16(x);
    h = __bfloat16_as_ushort(hb);
    l = __bfloat16_as_ushort(__float2bfloat16(x - __bfloat162float(hb)));
}
__device__ __forceinline__ void cvt_pair(float x0, float x1, u32& hi, u32& lo) {
    u16 h0, l0, h1, l1;
    split1(x0, h0, l0); split1(x1, h1, l1);
    hi = (u32)h0 | ((u32)h1 << 16);
    lo = (u32)l0 | ((u32)l1 << 16);
}
__device__ __forceinline__ u32 pack_bf16(float a, float b) {
    u16 ha = __bfloat16_as_ushort(__float2bfloat16(a));
    u16 hb = __bfloat16_as_ushort(__float2bfloat16(b));
    return (u32)ha | ((u32)hb << 16);
}
__device__ __forceinline__ void ldsm4(u32* r, u32 addr) {
    asm volatile("ldmatrix.sync.aligned.m8n8.x4.shared.b16 {%0,%1,%2,%3}, [%4];"
                 : "=r"(r[0]), "=r"(r[1]), "=r"(r[2]), "=r"(r[3]) : "r"(addr));
}
__device__ __forceinline__ void mma_bf16(float* c, const u32* a, const u32* b) {
    asm volatile("mma.sync.aligned.m16n8k16.row.col.f32.bf16.bf16.f32 "
                 "{%0,%1,%2,%3},{%4,%5,%6,%7},{%8,%9},{%0,%1,%2,%3};"
                 : "+f"(c[0]), "+f"(c[1]), "+f"(c[2]), "+f"(c[3])
                 : "r"(a[0]), "r"(a[1]), "r"(a[2]), "r"(a[3]), "r"(b[0]), "r"(b[1]));
}
__device__ __forceinline__ void cp16(u32 dst, const void* src) {
    asm volatile("cp.async.cg.shared.global [%0], [%1], 16;" :: "r"(dst), "l"(src));
}
#define CP_COMMIT() asm volatile("cp.async.commit_group;")
#define CP_WAIT(n)  asm volatile("cp.async.wait_group %0;" :: "n"(n))

__device__ __forceinline__ int swz(int r, int byteoff) {
    return r * 128 + (byteoff ^ ((r & 7) << 4));
}

// ---------------------------------------------------------------------------
// GroupNorm -> split-bf16, transposed to [b][l][c]
// ---------------------------------------------------------------------------
__global__ void gn_kernel(const float* __restrict__ x,
                          const float* __restrict__ gamma,
                          const float* __restrict__ beta)
{
    int b = blockIdx.x >> 5;
    int g = blockIdx.x & 31;
    size_t base = (size_t)(b * C_ + g * 16) * L_;
    const float4* xb = reinterpret_cast<const float4*>(x + base);
    int tid = threadIdx.x;

    float s = 0.f, s2 = 0.f;
    for (int i = tid; i < 4096; i += 256) {
        float4 v = xb[i];
        s  += v.x + v.y + v.z + v.w;
        s2 += v.x*v.x + v.y*v.y + v.z*v.z + v.w*v.w;
    }
    __shared__ float rs[256], rs2[256];
    rs[tid] = s; rs2[tid] = s2;
    __syncthreads();
    for (int off = 128; off > 0; off >>= 1) {
        if (tid < off) { rs[tid] += rs[tid+off]; rs2[tid] += rs2[tid+off]; }
        __syncthreads();
    }
    __shared__ float smean, sinv;
    if (tid == 0) {
        float mean = rs[0] * (1.f / 16384.f);
        float var  = rs2[0] * (1.f / 16384.f) - mean * mean;
        smean = mean;
        sinv  = rsqrtf(var + 1e-5f);
    }
    __syncthreads();
    float mean = smean, inv = sinv;

    __shared__ u16 sh_h[16][258];
    __shared__ u16 sh_l[16][258];

#pragma unroll 1
    for (int chunk = 0; chunk < 4; chunk++) {
        int l0 = chunk * 256;
#pragma unroll 1
        for (int cc = 0; cc < 16; cc++) {
            int c = g * 16 + cc;
            float ga = gamma[c] * inv;
            float bt = beta[c] - mean * ga;
            float v = x[base + (size_t)cc * 1024 + l0 + tid];
            float y = v * ga + bt;
            u16 h, l;
            split1(y, h, l);
            sh_h[cc][tid] = h;
            sh_l[cc][tid] = l;
        }
        __syncthreads();
        int c = tid & 15, lq = tid >> 4;
#pragma unroll
        for (int step = 0; step < 16; step++) {
            int ll = step * 16 + lq;
            size_t o = ((size_t)b * 1024 + l0 + ll) * 512 + g * 16 + c;
            g_xnt_h[o] = sh_h[c][ll];
            g_xnt_l[o] = sh_l[c][ll];
        }
        __syncthreads();
    }
}

// ---------------------------------------------------------------------------
__global__ void wconv_kernel(const float* __restrict__ w0, const float* __restrict__ w1,
                             const float* __restrict__ w2, const float* __restrict__ w3)
{
    int ws = blockIdx.y;
    const float* W = (ws == 0) ? w0 : (ws == 1) ? w1 : (ws == 2) ? w2 : w3;
    int i = (blockIdx.x * 256 + threadIdx.x) * 4;
    float4 v = *(const float4*)&W[i];
    u32 h0, l0, h1, l1;
    cvt_pair(v.x, v.y, h0, l0);
    cvt_pair(v.z, v.w, h1, l1);
    size_t o = (size_t)ws * 262144 + i;
    *(u32*)&g_wh[o] = h0; *(u32*)&g_wh[o + 2] = h1;
    *(u32*)&g_wl[o] = l0; *(u32*)&g_wl[o + 2] = l1;
}

// ---------------------------------------------------------------------------
// Pipelined split-bf16 GEMM (2-stage cp.async ping-pong).
// Race-free: the bottom __syncthreads releases stage (it-1)&1 before any
// warp reaches the next load_stage issue.
// ---------------------------------------------------------------------------
#define GST 24576   // stage stride in u16

__global__ void __launch_bounds__(256) gemm_mma(const float* __restrict__ bias0,
                                                const float* __restrict__ bias1,
                                                const float* __restrict__ bias2,
                                                const float* __restrict__ resid,
                                                float* __restrict__ extout,
                                                int qkv)
{
    extern __shared__ __align__(16) u16 dsm[];
    u32 sm = (u32)__cvta_generic_to_shared(dsm);

    int mode, mblk;
    const float* bias;
    if (qkv) {
        mode = blockIdx.y >> 2;
        mblk = blockIdx.y & 3;
        bias = (mode == 0) ? bias0 : (mode == 1) ? bias1 : bias2;
    } else {
        mode = 3;
        mblk = blockIdx.y;
        bias = bias0;
    }
    bool full3 = (mode < 2);

    int b  = blockIdx.z;
    int n0 = blockIdx.x * 64;
    int m0 = mblk * 128;
    const u16* Ah = g_wh + (size_t)mode * 262144;
    const u16* Al = g_wl + (size_t)mode * 262144;
    const u16* Bh = ((mode == 3) ? g_ah : g_xnt_h) + (size_t)b * 524288;
    const u16* Bl = ((mode == 3) ? g_al : g_xnt_l) + (size_t)b * 524288;

    int tid = threadIdx.x, wid = tid >> 5, lane = tid & 31;
    int wm = wid & 1, wn = wid >> 1;

    float acc[4][2][4] = {};

    int alr = lane & 15, ahalf = (lane >> 4) * 8;
    int bn = (lane >> 4) * 8 + (lane & 7);
    int bk = ((lane >> 3) & 1) * 8;

    auto load_stage = [&](int stage, int k0) {
        u32 sa_h = sm + (u32)(stage * GST) * 2;
        u32 sa_l = sa_h + 8192 * 2;
        u32 sb_h = sa_h + 16384 * 2;
        u32 sb_l = sa_h + 20480 * 2;
#pragma unroll
        for (int j = 0; j < 4; j++) {
            int idx = j * 256 + tid;
            int row = idx >> 3, ch = idx & 7;
            size_t off = (size_t)(m0 + row) * 512 + k0 + ch * 8;
            int so = swz(row, ch * 16);
            cp16(sa_h + so, Ah + off);
            cp16(sa_l + so, Al + off);
        }
#pragma unroll
        for (int j = 0; j < 2; j++) {
            int idx = j * 256 + tid;
            int row = idx >> 3, ch = idx & 7;
            size_t off = (size_t)(n0 + row) * 512 + k0 + ch * 8;
            int so = swz(row, ch * 16);
            cp16(sb_h + so, Bh + off);
            cp16(sb_l + so, Bl + off);
        }
        CP_COMMIT();
    };

    load_stage(0, 0);

#pragma unroll 1
    for (int it = 0; it < 8; it++) {
        if (it + 1 < 8) load_stage((it + 1) & 1, (it + 1) * 64);
        if (it + 1 < 8) { CP_WAIT(1); } else { CP_WAIT(0); }
        __syncthreads();

        u32 sa_h = sm + (u32)((it & 1) * GST) * 2;
        u32 sa_l = sa_h + 8192 * 2;
        u32 sb_h = sa_h + 16384 * 2;
        u32 sb_l = sa_h + 20480 * 2;

#pragma unroll
        for (int ks = 0; ks < 64; ks += 16) {
            u32 af[2][4][4], bf[2][4];
#pragma unroll
            for (int mt = 0; mt < 4; mt++) {
                int so = swz(wm * 64 + mt * 16 + alr, (ks + ahalf) * 2);
                ldsm4(af[0][mt], sa_h + so);
                ldsm4(af[1][mt], sa_l + so);
            }
            {
                int so = swz(wn * 16 + bn, (ks + bk) * 2);
                ldsm4(bf[0], sb_h + so);
                ldsm4(bf[1], sb_l + so);
            }
#pragma unroll
            for (int mt = 0; mt < 4; mt++)
#pragma unroll
                for (int nt = 0; nt < 2; nt++)
                    mma_bf16(acc[mt][nt], af[0][mt], &bf[0][nt * 2]);
#pragma unroll
            for (int mt = 0; mt < 4; mt++)
#pragma unroll
                for (int nt = 0; nt < 2; nt++)
                    mma_bf16(acc[mt][nt], af[0][mt], &bf[1][nt * 2]);
            if (full3) {
#pragma unroll
                for (int mt = 0; mt < 4; mt++)
#pragma unroll
                    for (int nt = 0; nt < 2; nt++)
                        mma_bf16(acc[mt][nt], af[1][mt], &bf[0][nt * 2]);
            }
        }
        __syncthreads();   // releases stage it&1 before next iter's load issue
    }

    // ---- epilogue ----
    const float scale = 0.35355339059327373f;
    int lr = lane >> 2, lc = (lane & 3) * 2;
#pragma unroll
    for (int mt = 0; mt < 4; mt++)
#pragma unroll
        for (int nt = 0; nt < 2; nt++) {
            int m = m0 + wm * 64 + mt * 16 + lr;
            int n = n0 + wn * 16 + nt * 8 + lc;
            float bi0 = bias[m], bi1 = bias[m + 8];
            float c0 = acc[mt][nt][0] + bi0, c1 = acc[mt][nt][1] + bi0;
            float c2 = acc[mt][nt][2] + bi1, c3 = acc[mt][nt][3] + bi1;
            if (mode == 3) {
                size_t o0 = ((size_t)b * 512 + m) * 1024 + n;
                size_t o1 = ((size_t)b * 512 + m + 8) * 1024 + n;
                float2 r0 = *(const float2*)&resid[o0];
                float2 r1 = *(const float2*)&resid[o1];
                *(float2*)&extout[o0] = make_float2(c0 + r0.x, c1 + r0.y);
                *(float2*)&extout[o1] = make_float2(c2 + r1.x, c3 + r1.y);
            } else if (mode == 2) {
                int bh = b * 8 + (m >> 6), d = m & 63;
                size_t o0 = ((size_t)bh * 64 + d) * 1024 + n;
                size_t o1 = ((size_t)bh * 64 + d + 8) * 1024 + n;
                *(u32*)&g_vh[o0] = pack_bf16(c0, c1);
                *(u32*)&g_vh[o1] = pack_bf16(c2, c3);
            } else {
                u16* dh = (mode == 0) ? g_qh : g_kh;
                u16* dl = (mode == 0) ? g_ql : g_kl;
                int bh = b * 8 + (m >> 6), d = m & 63;
                size_t base = (size_t)bh * 1024;
                u16 h, l;
                split1(c0 * scale, h, l);
                dh[(base + n) * 64 + d] = h;     dl[(base + n) * 64 + d] = l;
                split1(c1 * scale, h, l);
                dh[(base + n + 1) * 64 + d] = h; dl[(base + n + 1) * 64 + d] = l;
                split1(c2 * scale, h, l);
                dh[(base + n) * 64 + d + 8] = h;     dl[(base + n) * 64 + d + 8] = l;
                split1(c3 * scale, h, l);
                dh[(base + n + 1) * 64 + d + 8] = h; dl[(base + n + 1) * 64 + d + 8] = l;
            }
        }
}

// ---------------------------------------------------------------------------
// Attention, register-resident SPLIT P, RACE-FREE pipeline:
// the KV load for stage it+1 is issued AFTER the top __syncthreads of iter
// it (which guarantees every warp finished iter it-1 — the last reader of
// that buffer), and still overlaps with compute of iter it.
// smem (u16): q_h 0, q_l 8192, stage s at 16384+s*12288: {k_h, k_l +4096,
// v_h +8192}.  Total 40960 u16 = 80 KB.
// ---------------------------------------------------------------------------
__global__ void __launch_bounds__(256, 2) attn_mma(float* __restrict__ attn_out)
{
    extern __shared__ __align__(16) u16 dsm[];
    u32 sm = (u32)__cvta_generic_to_shared(dsm);
    u32 qs0 = sm, qs1 = sm + 8192 * 2;

    int bh = blockIdx.y, t0 = blockIdx.x * 128;
    int b = bh >> 3, head = bh & 7;
    int tid = threadIdx.x, wid = tid >> 5, lane = tid & 31;

    // ---- Q tile: 128 rows x 64 cols, both splits ----
#pragma unroll
    for (int j = 0; j < 4; j++) {
        int idx = j * 256 + tid;
        int row = idx >> 3, ch = idx & 7;
        size_t off = ((size_t)bh * 1024 + t0 + row) * 64 + ch * 8;
        int so = swz(row, ch * 16);
        cp16(qs0 + so, g_qh + off);
        cp16(qs1 + so, g_ql + off);
    }
    CP_COMMIT();

    auto load_kv = [&](int stage, int s0) {
        u32 kh = sm + (u32)(16384 + stage * 12288) * 2;
        u32 kl = kh + 4096 * 2;
        u32 vh = kh + 8192 * 2;
#pragma unroll
        for (int j = 0; j < 2; j++) {
            int idx = j * 256 + tid;
            int row = idx >> 3, ch = idx & 7;
            int so = swz(row, ch * 16);
            size_t ko = ((size_t)bh * 1024 + s0 + row) * 64 + ch * 8;
            cp16(kh + so, g_kh + ko);
            cp16(kl + so, g_kl + ko);
            size_t vo = ((size_t)bh * 64 + row) * 1024 + s0 + ch * 8;
            cp16(vh + so, g_vh + vo);
        }
        CP_COMMIT();
    };

    load_kv(0, 0);

    float avacc[8][4] = {};          // t16 x d64: 8 n8-tiles
    float lsum0 = 0.f, lsum1 = 0.f;  // row sums (rows lr, lr+8)

    int alr = lane & 15, ahalf = (lane >> 4) * 8;
    int bn = (lane >> 4) * 8 + (lane & 7);
    int bkk = ((lane >> 3) & 1) * 8;
    int lr = lane >> 2, lc = (lane & 3) * 2;
    int trow = wid * 16;             // warp's t base within CTA

#pragma unroll 1
    for (int it = 0; it < 16; it++) {
        int s0 = it * 64;
        CP_WAIT(0);          // stage it&1 data arrived
        __syncthreads();     // every warp finished iter it-1 (released (it+1)&1)
        if (it + 1 < 16) load_kv((it + 1) & 1, s0 + 64);   // safe: buffer free

        u32 kh = sm + (u32)(16384 + (it & 1) * 12288) * 2;
        u32 kl = kh + 4096 * 2;
        u32 vh = kh + 8192 * 2;

        // ---- S = Q K^T : warp tile 16t x 64s ----
        float sacc[8][4] = {};
#pragma unroll
        for (int kd = 0; kd < 64; kd += 16) {
            u32 afq0[4], afq1[4];
            {
                int so = swz(trow + alr, (kd + ahalf) * 2);
                ldsm4(afq0, qs0 + so);
                ldsm4(afq1, qs1 + so);
            }
#pragma unroll
            for (int g = 0; g < 4; g++) {
                u32 bk_h[4], bk_l[4];
                int so = swz(g * 16 + bn, (kd + bkk) * 2);
                ldsm4(bk_h, kh + so);
                ldsm4(bk_l, kl + so);
                mma_bf16(sacc[2*g],   afq0, &bk_h[0]);
                mma_bf16(sacc[2*g+1], afq0, &bk_h[2]);
                mma_bf16(sacc[2*g],   afq0, &bk_l[0]);
                mma_bf16(sacc[2*g+1], afq0, &bk_l[2]);
                mma_bf16(sacc[2*g],   afq1, &bk_h[0]);
                mma_bf16(sacc[2*g+1], afq1, &bk_h[2]);
            }
        }

        // ---- dump raw scores, exp, row sums, repack SPLIT P ----
        u32 prh0[8], prh1[8], prl0[8], prl1[8];
        {
            size_t base = (size_t)bh * 1048576 + (size_t)(t0 + trow + lr) * 1024 + s0 + lc;
#pragma unroll
            for (int nt = 0; nt < 8; nt++) {
                __stcs((float2*)&attn_out[base + nt * 8],
                       make_float2(sacc[nt][0], sacc[nt][1]));
                __stcs((float2*)&attn_out[base + 8192 + nt * 8],
                       make_float2(sacc[nt][2], sacc[nt][3]));
                float p0 = __expf(sacc[nt][0]);
                float p1 = __expf(sacc[nt][1]);
                float p2 = __expf(sacc[nt][2]);
                float p3 = __expf(sacc[nt][3]);
                lsum0 += p0 + p1;
                lsum1 += p2 + p3;
                cvt_pair(p0, p1, prh0[nt], prl0[nt]);
                cvt_pair(p2, p3, prh1[nt], prl1[nt]);
            }
        }

        // ---- AV: out(t,d) += (P_hi + P_lo)(t,s) * V(d,s)^T, P from regs ----
#pragma unroll
        for (int c = 0; c < 4; c++) {
            u32 aPh[4] = { prh0[2*c], prh1[2*c], prh0[2*c + 1], prh1[2*c + 1] };
            u32 aPl[4] = { prl0[2*c], prl1[2*c], prl0[2*c + 1], prl1[2*c + 1] };
#pragma unroll
            for (int g = 0; g < 4; g++) {
                u32 bv[4];
                int so = swz(g * 16 + bn, (c * 16 + bkk) * 2);
                ldsm4(bv, vh + so);
                mma_bf16(avacc[2*g],   aPh, &bv[0]);
                mma_bf16(avacc[2*g+1], aPh, &bv[2]);
                mma_bf16(avacc[2*g],   aPl, &bv[0]);
                mma_bf16(avacc[2*g+1], aPl, &bv[2]);
            }
        }
    }

    // ---- row sums within quad, normalize, store a (split bf16) ----
    lsum0 += __shfl_xor_sync(0xffffffffu, lsum0, 1);
    lsum0 += __shfl_xor_sync(0xffffffffu, lsum0, 2);
    lsum1 += __shfl_xor_sync(0xffffffffu, lsum1, 1);
    lsum1 += __shfl_xor_sync(0xffffffffu, lsum1, 2);
    float inv0 = 1.f / lsum0;
    float inv1 = 1.f / lsum1;

#pragma unroll
    for (int dt = 0; dt < 8; dt++) {
        int dcol = head * 64 + dt * 8 + lc;
        u32 h0, l0, h1, l1;
        cvt_pair(avacc[dt][0] * inv0, avacc[dt][1] * inv0, h0, l0);
        cvt_pair(avacc[dt][2] * inv1, avacc[dt][3] * inv1, h1, l1);
        size_t o0 = ((size_t)b * 1024 + t0 + trow + lr) * 512 + dcol;
        size_t o1 = ((size_t)b * 1024 + t0 + trow + lr + 8) * 512 + dcol;
        *(u32*)&g_ah[o0] = h0; *(u32*)&g_al[o0] = l0;
        *(u32*)&g_ah[o1] = h1; *(u32*)&g_al[o1] = l1;
    }
}

// ---------------------------------------------------------------------------
extern "C" void kernel_launch(void* const* d_in, const int* in_sizes, int n_in,
                              void* d_out, int out_size)
{
    const float* x     = (const float*)d_in[0];
    const float* gamma = (const float*)d_in[2];
    const float* beta  = (const float*)d_in[3];
    const float* Wq    = (const float*)d_in[4];
    const float* bq    = (const float*)d_in[5];
    const float* Wk    = (const float*)d_in[6];
    const float* bk    = (const float*)d_in[7];
    const float* Wv    = (const float*)d_in[8];
    const float* bv    = (const float*)d_in[9];
    const float* Wo    = (const float*)d_in[10];
    const float* bo    = (const float*)d_in[11];

    float* out = (float*)d_out;
    float* attn_out;
    if ((long long)out_size >= (long long)BCL + (long long)ATT) {
        attn_out = out + (size_t)BCL;
    } else {
        float* sink;
        cudaGetSymbolAddress((void**)&sink, g_attn_sink);
        attn_out = sink;
    }

    const int GEMM_SMEM = 96 * 1024;
    const int ATTN_SMEM = 80 * 1024;
    cudaFuncSetAttribute(gemm_mma, cudaFuncAttributeMaxDynamicSharedMemorySize, GEMM_SMEM);
    cudaFuncSetAttribute(attn_mma, cudaFuncAttributeMaxDynamicSharedMemorySize, ATTN_SMEM);

    gn_kernel<<<256, 256>>>(x, gamma, beta);
    wconv_kernel<<<dim3(256, 4), 256>>>(Wq, Wk, Wv, Wo);

    // fused QKV projections
    gemm_mma<<<dim3(16, 12, B_), 256, GEMM_SMEM>>>(bq, bk, bv, nullptr, nullptr, 1);

    attn_mma<<<dim3(8, 64), 256, ATTN_SMEM>>>(attn_out);

    gemm_mma<<<dim3(16, 4, B_), 256, GEMM_SMEM>>>(bo, nullptr, nullptr, x, out, 0);
}

// round 16
// speedup vs baseline: 1.0577x; 1.0577x over previous
#include <cuda_runtime.h>
#include <cuda_bf16.h>
#include <stdint.h>

#define B_  8
#define C_  512
#define L_  1024
#define BCL (B_*C_*L_)               // 4194304
#define ATT (64*1024*1024)

typedef unsigned short u16;
typedef unsigned int   u32;

// Scratch (device globals; allocation-free per harness rules)
__device__ __align__(16) u16 g_xnt_h[BCL];  // xn split-hi, [b][l][c]
__device__ __align__(16) u16 g_xnt_l[BCL];
__device__ __align__(16) u16 g_wh[4*C_*C_];
__device__ __align__(16) u16 g_wl[4*C_*C_];
__device__ __align__(16) u16 g_qh[BCL], g_ql[BCL];   // [bh][t][d] (scaled)
__device__ __align__(16) u16 g_kh[BCL], g_kl[BCL];   // [bh][s][d] (scaled)
__device__ __align__(16) u16 g_vh[BCL];              // [bh][d][s] (bf16 only)
__device__ __align__(16) u16 g_ah[BCL], g_al[BCL];   // [b][t][inner]
__device__ __align__(16) float g_attn_sink[ATT];

// ---------------------------------------------------------------------------
__device__ __forceinline__ void split1(float x, u16& h, u16& l) {
    __nv_bfloat16 hb = __float2bfloat16(x);
    h = __bfloat16_as_ushort(hb);
    l = __bfloat16_as_ushort(__float2bfloat16(x - __bfloat162float(hb)));
}
__device__ __forceinline__ void cvt_pair(float x0, float x1, u32& hi, u32& lo) {
    u16 h0, l0, h1, l1;
    split1(x0, h0, l0); split1(x1, h1, l1);
    hi = (u32)h0 | ((u32)h1 << 16);
    lo = (u32)l0 | ((u32)l1 << 16);
}
__device__ __forceinline__ u32 pack_bf16(float a, float b) {
    u16 ha = __bfloat16_as_ushort(__float2bfloat16(a));
    u16 hb = __bfloat16_as_ushort(__float2bfloat16(b));
    return (u32)ha | ((u32)hb << 16);
}
// single-instruction pack: lo -> bits[0:16), hi -> bits[16:32)
__device__ __forceinline__ u32 packcvt(float lo_e, float hi_e) {
    u32 r;
    asm("cvt.rn.bf16x2.f32 %0, %1, %2;" : "=r"(r) : "f"(hi_e), "f"(lo_e));
    return r;
}
__device__ __forceinline__ void ldsm4(u32* r, u32 addr) {
    asm volatile("ldmatrix.sync.aligned.m8n8.x4.shared.b16 {%0,%1,%2,%3}, [%4];"
                 : "=r"(r[0]), "=r"(r[1]), "=r"(r[2]), "=r"(r[3]) : "r"(addr));
}
__device__ __forceinline__ void mma_bf16(float* c, const u32* a, const u32* b) {
    asm volatile("mma.sync.aligned.m16n8k16.row.col.f32.bf16.bf16.f32 "
                 "{%0,%1,%2,%3},{%4,%5,%6,%7},{%8,%9},{%0,%1,%2,%3};"
                 : "+f"(c[0]), "+f"(c[1]), "+f"(c[2]), "+f"(c[3])
                 : "r"(a[0]), "r"(a[1]), "r"(a[2]), "r"(a[3]), "r"(b[0]), "r"(b[1]));
}
__device__ __forceinline__ void cp16(u32 dst, const void* src) {
    asm volatile("cp.async.cg.shared.global [%0], [%1], 16;" :: "r"(dst), "l"(src));
}
#define CP_COMMIT() asm volatile("cp.async.commit_group;")
#define CP_WAIT(n)  asm volatile("cp.async.wait_group %0;" :: "n"(n))

__device__ __forceinline__ int swz(int r, int byteoff) {
    return r * 128 + (byteoff ^ ((r & 7) << 4));
}

// ---------------------------------------------------------------------------
// GroupNorm -> split-bf16, transposed to [b][l][c]
// ---------------------------------------------------------------------------
__global__ void gn_kernel(const float* __restrict__ x,
                          const float* __restrict__ gamma,
                          const float* __restrict__ beta)
{
    int b = blockIdx.x >> 5;
    int g = blockIdx.x & 31;
    size_t base = (size_t)(b * C_ + g * 16) * L_;
    const float4* xb = reinterpret_cast<const float4*>(x + base);
    int tid = threadIdx.x;

    float s = 0.f, s2 = 0.f;
    for (int i = tid; i < 4096; i += 256) {
        float4 v = xb[i];
        s  += v.x + v.y + v.z + v.w;
        s2 += v.x*v.x + v.y*v.y + v.z*v.z + v.w*v.w;
    }
    __shared__ float rs[256], rs2[256];
    rs[tid] = s; rs2[tid] = s2;
    __syncthreads();
    for (int off = 128; off > 0; off >>= 1) {
        if (tid < off) { rs[tid] += rs[tid+off]; rs2[tid] += rs2[tid+off]; }
        __syncthreads();
    }
    __shared__ float smean, sinv;
    if (tid == 0) {
        float mean = rs[0] * (1.f / 16384.f);
        float var  = rs2[0] * (1.f / 16384.f) - mean * mean;
        smean = mean;
        sinv  = rsqrtf(var + 1e-5f);
    }
    __syncthreads();
    float mean = smean, inv = sinv;

    __shared__ u16 sh_h[16][258];
    __shared__ u16 sh_l[16][258];

#pragma unroll 1
    for (int chunk = 0; chunk < 4; chunk++) {
        int l0 = chunk * 256;
#pragma unroll 1
        for (int cc = 0; cc < 16; cc++) {
            int c = g * 16 + cc;
            float ga = gamma[c] * inv;
            float bt = beta[c] - mean * ga;
            float v = x[base + (size_t)cc * 1024 + l0 + tid];
            float y = v * ga + bt;
            u16 h, l;
            split1(y, h, l);
            sh_h[cc][tid] = h;
            sh_l[cc][tid] = l;
        }
        __syncthreads();
        int c = tid & 15, lq = tid >> 4;
#pragma unroll
        for (int step = 0; step < 16; step++) {
            int ll = step * 16 + lq;
            size_t o = ((size_t)b * 1024 + l0 + ll) * 512 + g * 16 + c;
            g_xnt_h[o] = sh_h[c][ll];
            g_xnt_l[o] = sh_l[c][ll];
        }
        __syncthreads();
    }
}

// ---------------------------------------------------------------------------
__global__ void wconv_kernel(const float* __restrict__ w0, const float* __restrict__ w1,
                             const float* __restrict__ w2, const float* __restrict__ w3)
{
    int ws = blockIdx.y;
    const float* W = (ws == 0) ? w0 : (ws == 1) ? w1 : (ws == 2) ? w2 : w3;
    int i = (blockIdx.x * 256 + threadIdx.x) * 4;
    float4 v = *(const float4*)&W[i];
    u32 h0, l0, h1, l1;
    cvt_pair(v.x, v.y, h0, l0);
    cvt_pair(v.z, v.w, h1, l1);
    size_t o = (size_t)ws * 262144 + i;
    *(u32*)&g_wh[o] = h0; *(u32*)&g_wh[o + 2] = h1;
    *(u32*)&g_wl[o] = l0; *(u32*)&g_wl[o + 2] = l1;
}

// ---------------------------------------------------------------------------
// Pipelined split-bf16 GEMM (2-stage cp.async ping-pong).  Race-free.
// ---------------------------------------------------------------------------
#define GST 24576   // stage stride in u16

__global__ void __launch_bounds__(256) gemm_mma(const float* __restrict__ bias0,
                                                const float* __restrict__ bias1,
                                                const float* __restrict__ bias2,
                                                const float* __restrict__ resid,
                                                float* __restrict__ extout,
                                                int qkv)
{
    extern __shared__ __align__(16) u16 dsm[];
    u32 sm = (u32)__cvta_generic_to_shared(dsm);

    int mode, mblk;
    const float* bias;
    if (qkv) {
        mode = blockIdx.y >> 2;
        mblk = blockIdx.y & 3;
        bias = (mode == 0) ? bias0 : (mode == 1) ? bias1 : bias2;
    } else {
        mode = 3;
        mblk = blockIdx.y;
        bias = bias0;
    }
    bool full3 = (mode < 2);

    int b  = blockIdx.z;
    int n0 = blockIdx.x * 64;
    int m0 = mblk * 128;
    const u16* Ah = g_wh + (size_t)mode * 262144;
    const u16* Al = g_wl + (size_t)mode * 262144;
    const u16* Bh = ((mode == 3) ? g_ah : g_xnt_h) + (size_t)b * 524288;
    const u16* Bl = ((mode == 3) ? g_al : g_xnt_l) + (size_t)b * 524288;

    int tid = threadIdx.x, wid = tid >> 5, lane = tid & 31;
    int wm = wid & 1, wn = wid >> 1;

    float acc[4][2][4] = {};

    int alr = lane & 15, ahalf = (lane >> 4) * 8;
    int bn = (lane >> 4) * 8 + (lane & 7);
    int bk = ((lane >> 3) & 1) * 8;

    auto load_stage = [&](int stage, int k0) {
        u32 sa_h = sm + (u32)(stage * GST) * 2;
        u32 sa_l = sa_h + 8192 * 2;
        u32 sb_h = sa_h + 16384 * 2;
        u32 sb_l = sa_h + 20480 * 2;
#pragma unroll
        for (int j = 0; j < 4; j++) {
            int idx = j * 256 + tid;
            int row = idx >> 3, ch = idx & 7;
            size_t off = (size_t)(m0 + row) * 512 + k0 + ch * 8;
            int so = swz(row, ch * 16);
            cp16(sa_h + so, Ah + off);
            cp16(sa_l + so, Al + off);
        }
#pragma unroll
        for (int j = 0; j < 2; j++) {
            int idx = j * 256 + tid;
            int row = idx >> 3, ch = idx & 7;
            size_t off = (size_t)(n0 + row) * 512 + k0 + ch * 8;
            int so = swz(row, ch * 16);
            cp16(sb_h + so, Bh + off);
            cp16(sb_l + so, Bl + off);
        }
        CP_COMMIT();
    };

    load_stage(0, 0);

#pragma unroll 1
    for (int it = 0; it < 8; it++) {
        if (it + 1 < 8) load_stage((it + 1) & 1, (it + 1) * 64);
        if (it + 1 < 8) { CP_WAIT(1); } else { CP_WAIT(0); }
        __syncthreads();

        u32 sa_h = sm + (u32)((it & 1) * GST) * 2;
        u32 sa_l = sa_h + 8192 * 2;
        u32 sb_h = sa_h + 16384 * 2;
        u32 sb_l = sa_h + 20480 * 2;

#pragma unroll
        for (int ks = 0; ks < 64; ks += 16) {
            u32 af[2][4][4], bf[2][4];
#pragma unroll
            for (int mt = 0; mt < 4; mt++) {
                int so = swz(wm * 64 + mt * 16 + alr, (ks + ahalf) * 2);
                ldsm4(af[0][mt], sa_h + so);
                ldsm4(af[1][mt], sa_l + so);
            }
            {
                int so = swz(wn * 16 + bn, (ks + bk) * 2);
                ldsm4(bf[0], sb_h + so);
                ldsm4(bf[1], sb_l + so);
            }
#pragma unroll
            for (int mt = 0; mt < 4; mt++)
#pragma unroll
                for (int nt = 0; nt < 2; nt++)
                    mma_bf16(acc[mt][nt], af[0][mt], &bf[0][nt * 2]);
#pragma unroll
            for (int mt = 0; mt < 4; mt++)
#pragma unroll
                for (int nt = 0; nt < 2; nt++)
                    mma_bf16(acc[mt][nt], af[0][mt], &bf[1][nt * 2]);
            if (full3) {
#pragma unroll
                for (int mt = 0; mt < 4; mt++)
#pragma unroll
                    for (int nt = 0; nt < 2; nt++)
                        mma_bf16(acc[mt][nt], af[1][mt], &bf[0][nt * 2]);
            }
        }
        __syncthreads();   // releases stage it&1 before next iter's load issue
    }

    // ---- epilogue ----
    const float scale = 0.35355339059327373f;
    int lr = lane >> 2, lc = (lane & 3) * 2;
#pragma unroll
    for (int mt = 0; mt < 4; mt++)
#pragma unroll
        for (int nt = 0; nt < 2; nt++) {
            int m = m0 + wm * 64 + mt * 16 + lr;
            int n = n0 + wn * 16 + nt * 8 + lc;
            float bi0 = bias[m], bi1 = bias[m + 8];
            float c0 = acc[mt][nt][0] + bi0, c1 = acc[mt][nt][1] + bi0;
            float c2 = acc[mt][nt][2] + bi1, c3 = acc[mt][nt][3] + bi1;
            if (mode == 3) {
                size_t o0 = ((size_t)b * 512 + m) * 1024 + n;
                size_t o1 = ((size_t)b * 512 + m + 8) * 1024 + n;
                float2 r0 = *(const float2*)&resid[o0];
                float2 r1 = *(const float2*)&resid[o1];
                *(float2*)&extout[o0] = make_float2(c0 + r0.x, c1 + r0.y);
                *(float2*)&extout[o1] = make_float2(c2 + r1.x, c3 + r1.y);
            } else if (mode == 2) {
                int bh = b * 8 + (m >> 6), d = m & 63;
                size_t o0 = ((size_t)bh * 64 + d) * 1024 + n;
                size_t o1 = ((size_t)bh * 64 + d + 8) * 1024 + n;
                *(u32*)&g_vh[o0] = pack_bf16(c0, c1);
                *(u32*)&g_vh[o1] = pack_bf16(c2, c3);
            } else {
                u16* dh = (mode == 0) ? g_qh : g_kh;
                u16* dl = (mode == 0) ? g_ql : g_kl;
                int bh = b * 8 + (m >> 6), d = m & 63;
                size_t base = (size_t)bh * 1024;
                u16 h, l;
                split1(c0 * scale, h, l);
                dh[(base + n) * 64 + d] = h;     dl[(base + n) * 64 + d] = l;
                split1(c1 * scale, h, l);
                dh[(base + n + 1) * 64 + d] = h; dl[(base + n + 1) * 64 + d] = l;
                split1(c2 * scale, h, l);
                dh[(base + n) * 64 + d + 8] = h;     dl[(base + n) * 64 + d + 8] = l;
                split1(c3 * scale, h, l);
                dh[(base + n + 1) * 64 + d + 8] = h; dl[(base + n + 1) * 64 + d + 8] = l;
            }
        }
}

// ---------------------------------------------------------------------------
// Attention, register-resident P (hi only), race-free pipeline:
// KV load for stage it+1 issued AFTER the top __syncthreads of iter it.
// S = QK^T keeps the full 3-MMA split (feeds attn_map, the strict output).
// AV = P_hi x V_hi, 1 MMA; single-instruction bf16x2 packs for the repack.
// smem (u16): q_h 0, q_l 8192, stage s at 16384+s*12288: {k_h, k_l +4096,
// v_h +8192}.  Total 40960 u16 = 80 KB.
// ---------------------------------------------------------------------------
__global__ void __launch_bounds__(256, 2) attn_mma(float* __restrict__ attn_out)
{
    extern __shared__ __align__(16) u16 dsm[];
    u32 sm = (u32)__cvta_generic_to_shared(dsm);
    u32 qs0 = sm, qs1 = sm + 8192 * 2;

    int bh = blockIdx.y, t0 = blockIdx.x * 128;
    int b = bh >> 3, head = bh & 7;
    int tid = threadIdx.x, wid = tid >> 5, lane = tid & 31;

    // ---- Q tile: 128 rows x 64 cols, both splits ----
#pragma unroll
    for (int j = 0; j < 4; j++) {
        int idx = j * 256 + tid;
        int row = idx >> 3, ch = idx & 7;
        size_t off = ((size_t)bh * 1024 + t0 + row) * 64 + ch * 8;
        int so = swz(row, ch * 16);
        cp16(qs0 + so, g_qh + off);
        cp16(qs1 + so, g_ql + off);
    }
    CP_COMMIT();

    auto load_kv = [&](int stage, int s0) {
        u32 kh = sm + (u32)(16384 + stage * 12288) * 2;
        u32 kl = kh + 4096 * 2;
        u32 vh = kh + 8192 * 2;
#pragma unroll
        for (int j = 0; j < 2; j++) {
            int idx = j * 256 + tid;
            int row = idx >> 3, ch = idx & 7;
            int so = swz(row, ch * 16);
            size_t ko = ((size_t)bh * 1024 + s0 + row) * 64 + ch * 8;
            cp16(kh + so, g_kh + ko);
            cp16(kl + so, g_kl + ko);
            size_t vo = ((size_t)bh * 64 + row) * 1024 + s0 + ch * 8;
            cp16(vh + so, g_vh + vo);
        }
        CP_COMMIT();
    };

    load_kv(0, 0);

    float avacc[8][4] = {};          // t16 x d64: 8 n8-tiles
    float lsum0 = 0.f, lsum1 = 0.f;  // row sums (rows lr, lr+8)

    int alr = lane & 15, ahalf = (lane >> 4) * 8;
    int bn = (lane >> 4) * 8 + (lane & 7);
    int bkk = ((lane >> 3) & 1) * 8;
    int lr = lane >> 2, lc = (lane & 3) * 2;
    int trow = wid * 16;             // warp's t base within CTA

#pragma unroll 1
    for (int it = 0; it < 16; it++) {
        int s0 = it * 64;
        CP_WAIT(0);          // stage it&1 data arrived
        __syncthreads();     // every warp finished iter it-1 (released (it+1)&1)
        if (it + 1 < 16) load_kv((it + 1) & 1, s0 + 64);   // safe: buffer free

        u32 kh = sm + (u32)(16384 + (it & 1) * 12288) * 2;
        u32 kl = kh + 4096 * 2;
        u32 vh = kh + 8192 * 2;

        // ---- S = Q K^T : warp tile 16t x 64s, full 3-MMA split ----
        float sacc[8][4] = {};
#pragma unroll
        for (int kd = 0; kd < 64; kd += 16) {
            u32 afq0[4], afq1[4];
            {
                int so = swz(trow + alr, (kd + ahalf) * 2);
                ldsm4(afq0, qs0 + so);
                ldsm4(afq1, qs1 + so);
            }
#pragma unroll
            for (int g = 0; g < 4; g++) {
                u32 bk_h[4], bk_l[4];
                int so = swz(g * 16 + bn, (kd + bkk) * 2);
                ldsm4(bk_h, kh + so);
                ldsm4(bk_l, kl + so);
                mma_bf16(sacc[2*g],   afq0, &bk_h[0]);
                mma_bf16(sacc[2*g+1], afq0, &bk_h[2]);
                mma_bf16(sacc[2*g],   afq0, &bk_l[0]);
                mma_bf16(sacc[2*g+1], afq0, &bk_l[2]);
                mma_bf16(sacc[2*g],   afq1, &bk_h[0]);
                mma_bf16(sacc[2*g+1], afq1, &bk_h[2]);
            }
        }

        // ---- dump raw scores, exp, row sums, repack P_hi (1-instr packs) ----
        u32 pr0[8], pr1[8];
        {
            size_t base = (size_t)bh * 1048576 + (size_t)(t0 + trow + lr) * 1024 + s0 + lc;
#pragma unroll
            for (int nt = 0; nt < 8; nt++) {
                __stcs((float2*)&attn_out[base + nt * 8],
                       make_float2(sacc[nt][0], sacc[nt][1]));
                __stcs((float2*)&attn_out[base + 8192 + nt * 8],
                       make_float2(sacc[nt][2], sacc[nt][3]));
                float p0 = __expf(sacc[nt][0]);
                float p1 = __expf(sacc[nt][1]);
                float p2 = __expf(sacc[nt][2]);
                float p3 = __expf(sacc[nt][3]);
                lsum0 += p0 + p1;
                lsum1 += p2 + p3;
                pr0[nt] = packcvt(p0, p1);
                pr1[nt] = packcvt(p2, p3);
            }
        }

        // ---- AV: out(t,d) += P_hi(t,s) * V(d,s)^T, P from registers ----
#pragma unroll
        for (int c = 0; c < 4; c++) {
            u32 aP[4] = { pr0[2*c], pr1[2*c], pr0[2*c + 1], pr1[2*c + 1] };
#pragma unroll
            for (int g = 0; g < 4; g++) {
                u32 bv[4];
                int so = swz(g * 16 + bn, (c * 16 + bkk) * 2);
                ldsm4(bv, vh + so);
                mma_bf16(avacc[2*g],   aP, &bv[0]);
                mma_bf16(avacc[2*g+1], aP, &bv[2]);
            }
        }
    }

    // ---- row sums within quad, normalize, store a (split bf16) ----
    lsum0 += __shfl_xor_sync(0xffffffffu, lsum0, 1);
    lsum0 += __shfl_xor_sync(0xffffffffu, lsum0, 2);
    lsum1 += __shfl_xor_sync(0xffffffffu, lsum1, 1);
    lsum1 += __shfl_xor_sync(0xffffffffu, lsum1, 2);
    float inv0 = 1.f / lsum0;
    float inv1 = 1.f / lsum1;

#pragma unroll
    for (int dt = 0; dt < 8; dt++) {
        int dcol = head * 64 + dt * 8 + lc;
        u32 h0, l0, h1, l1;
        cvt_pair(avacc[dt][0] * inv0, avacc[dt][1] * inv0, h0, l0);
        cvt_pair(avacc[dt][2] * inv1, avacc[dt][3] * inv1, h1, l1);
        size_t o0 = ((size_t)b * 1024 + t0 + trow + lr) * 512 + dcol;
        size_t o1 = ((size_t)b * 1024 + t0 + trow + lr + 8) * 512 + dcol;
        *(u32*)&g_ah[o0] = h0; *(u32*)&g_al[o0] = l0;
        *(u32*)&g_ah[o1] = h1; *(u32*)&g_al[o1] = l1;
    }
}

// ---------------------------------------------------------------------------
extern "C" void kernel_launch(void* const* d_in, const int* in_sizes, int n_in,
                              void* d_out, int out_size)
{
    const float* x     = (const float*)d_in[0];
    const float* gamma = (const float*)d_in[2];
    const float* beta  = (const float*)d_in[3];
    const float* Wq    = (const float*)d_in[4];
    const float* bq    = (const float*)d_in[5];
    const float* Wk    = (const float*)d_in[6];
    const float* bk    = (const float*)d_in[7];
    const float* Wv    = (const float*)d_in[8];
    const float* bv    = (const float*)d_in[9];
    const float* Wo    = (const float*)d_in[10];
    const float* bo    = (const float*)d_in[11];

    float* out = (float*)d_out;
    float* attn_out;
    if ((long long)out_size >= (long long)BCL + (long long)ATT) {
        attn_out = out + (size_t)BCL;
    } else {
        float* sink;
        cudaGetSymbolAddress((void**)&sink, g_attn_sink);
        attn_out = sink;
    }

    const int GEMM_SMEM = 96 * 1024;
    const int ATTN_SMEM = 80 * 1024;
    cudaFuncSetAttribute(gemm_mma, cudaFuncAttributeMaxDynamicSharedMemorySize, GEMM_SMEM);
    cudaFuncSetAttribute(attn_mma, cudaFuncAttributeMaxDynamicSharedMemorySize, ATTN_SMEM);

    gn_kernel<<<256, 256>>>(x, gamma, beta);
    wconv_kernel<<<dim3(256, 4), 256>>>(Wq, Wk, Wv, Wo);

    // fused QKV projections
    gemm_mma<<<dim3(16, 12, B_), 256, GEMM_SMEM>>>(bq, bk, bv, nullptr, nullptr, 1);

    attn_mma<<<dim3(8, 64), 256, ATTN_SMEM>>>(attn_out);

    gemm_mma<<<dim3(16, 4, B_), 256, GEMM_SMEM>>>(bo, nullptr, nullptr, x, out, 0);
}

// round 17
// speedup vs baseline: 1.0704x; 1.0120x over previous
#include <cuda_runtime.h>
#include <cuda_bf16.h>
#include <cuda_fp16.h>
#include <stdint.h>

#define B_  8
#define C_  512
#define L_  1024
#define BCL (B_*C_*L_)               // 4194304
#define ATT (64*1024*1024)

typedef unsigned short u16;
typedef unsigned int   u32;

// Scratch (device globals; allocation-free per harness rules)
__device__ __align__(16) u16 g_xnt_h[BCL];  // xn split-hi, [b][l][c]
__device__ __align__(16) u16 g_xnt_l[BCL];
__device__ __align__(16) u16 g_wh[4*C_*C_];
__device__ __align__(16) u16 g_wl[4*C_*C_];
__device__ __align__(16) u16 g_qh[BCL], g_ql[BCL];   // [bh][t][d] (scaled)
__device__ __align__(16) u16 g_kh[BCL], g_kl[BCL];   // [bh][s][d] (scaled)
__device__ __align__(16) u16 g_vh[BCL];              // [bh][d][s] (f16)
__device__ __align__(16) u16 g_ah[BCL], g_al[BCL];   // [b][t][inner]
__device__ __align__(16) float g_attn_sink[ATT];

// ---------------------------------------------------------------------------
__device__ __forceinline__ void split1(float x, u16& h, u16& l) {
    __nv_bfloat16 hb = __float2bfloat16(x);
    h = __bfloat16_as_ushort(hb);
    l = __bfloat16_as_ushort(__float2bfloat16(x - __bfloat162float(hb)));
}
__device__ __forceinline__ void cvt_pair(float x0, float x1, u32& hi, u32& lo) {
    u16 h0, l0, h1, l1;
    split1(x0, h0, l0); split1(x1, h1, l1);
    hi = (u32)h0 | ((u32)h1 << 16);
    lo = (u32)l0 | ((u32)l1 << 16);
}
// bf16x2 pack: lo_e -> bits[0:16), hi_e -> bits[16:32)
__device__ __forceinline__ u32 packcvt(float lo_e, float hi_e) {
    u32 r;
    asm("cvt.rn.bf16x2.f32 %0, %1, %2;" : "=r"(r) : "f"(hi_e), "f"(lo_e));
    return r;
}
// f16x2 pack: lo_e -> bits[0:16), hi_e -> bits[16:32)
__device__ __forceinline__ u32 pack_f16x2(float lo_e, float hi_e) {
    u32 r;
    asm("cvt.rn.f16x2.f32 %0, %1, %2;" : "=r"(r) : "f"(hi_e), "f"(lo_e));
    return r;
}
// packed exp2 on f16x2
__device__ __forceinline__ u32 ex2_f16x2(u32 a) {
    u32 r;
    asm("ex2.approx.f16x2 %0, %1;" : "=r"(r) : "r"(a));
    return r;
}
__device__ __forceinline__ void ldsm4(u32* r, u32 addr) {
    asm volatile("ldmatrix.sync.aligned.m8n8.x4.shared.b16 {%0,%1,%2,%3}, [%4];"
                 : "=r"(r[0]), "=r"(r[1]), "=r"(r[2]), "=r"(r[3]) : "r"(addr));
}
__device__ __forceinline__ void mma_bf16(float* c, const u32* a, const u32* b) {
    asm volatile("mma.sync.aligned.m16n8k16.row.col.f32.bf16.bf16.f32 "
                 "{%0,%1,%2,%3},{%4,%5,%6,%7},{%8,%9},{%0,%1,%2,%3};"
                 : "+f"(c[0]), "+f"(c[1]), "+f"(c[2]), "+f"(c[3])
                 : "r"(a[0]), "r"(a[1]), "r"(a[2]), "r"(a[3]), "r"(b[0]), "r"(b[1]));
}
__device__ __forceinline__ void mma_f16(float* c, const u32* a, const u32* b) {
    asm volatile("mma.sync.aligned.m16n8k16.row.col.f32.f16.f16.f32 "
                 "{%0,%1,%2,%3},{%4,%5,%6,%7},{%8,%9},{%0,%1,%2,%3};"
                 : "+f"(c[0]), "+f"(c[1]), "+f"(c[2]), "+f"(c[3])
                 : "r"(a[0]), "r"(a[1]), "r"(a[2]), "r"(a[3]), "r"(b[0]), "r"(b[1]));
}
__device__ __forceinline__ void cp16(u32 dst, const void* src) {
    asm volatile("cp.async.cg.shared.global [%0], [%1], 16;" :: "r"(dst), "l"(src));
}
#define CP_COMMIT() asm volatile("cp.async.commit_group;")
#define CP_WAIT(n)  asm volatile("cp.async.wait_group %0;" :: "n"(n))

__device__ __forceinline__ int swz(int r, int byteoff) {
    return r * 128 + (byteoff ^ ((r & 7) << 4));
}

// ---------------------------------------------------------------------------
// Fused prep: blocks [0,256) do GroupNorm -> split-bf16 [b][l][c];
// blocks [256,1280) convert the 4 weight matrices to split-bf16.
// ---------------------------------------------------------------------------
__global__ void prep_kernel(const float* __restrict__ x,
                            const float* __restrict__ gamma,
                            const float* __restrict__ beta,
                            const float* __restrict__ w0, const float* __restrict__ w1,
                            const float* __restrict__ w2, const float* __restrict__ w3)
{
    int tid = threadIdx.x;

    if (blockIdx.x >= 256) {
        int idx = blockIdx.x - 256;
        int ws = idx >> 8;
        const float* W = (ws == 0) ? w0 : (ws == 1) ? w1 : (ws == 2) ? w2 : w3;
        int i = ((idx & 255) * 256 + tid) * 4;
        float4 v = *(const float4*)&W[i];
        u32 h0, l0, h1, l1;
        cvt_pair(v.x, v.y, h0, l0);
        cvt_pair(v.z, v.w, h1, l1);
        size_t o = (size_t)ws * 262144 + i;
        *(u32*)&g_wh[o] = h0; *(u32*)&g_wh[o + 2] = h1;
        *(u32*)&g_wl[o] = l0; *(u32*)&g_wl[o + 2] = l1;
        return;
    }

    int b = blockIdx.x >> 5;
    int g = blockIdx.x & 31;
    size_t base = (size_t)(b * C_ + g * 16) * L_;
    const float4* xb = reinterpret_cast<const float4*>(x + base);

    float s = 0.f, s2 = 0.f;
    for (int i = tid; i < 4096; i += 256) {
        float4 v = xb[i];
        s  += v.x + v.y + v.z + v.w;
        s2 += v.x*v.x + v.y*v.y + v.z*v.z + v.w*v.w;
    }
    __shared__ float rs[256], rs2[256];
    rs[tid] = s; rs2[tid] = s2;
    __syncthreads();
    for (int off = 128; off > 0; off >>= 1) {
        if (tid < off) { rs[tid] += rs[tid+off]; rs2[tid] += rs2[tid+off]; }
        __syncthreads();
    }
    __shared__ float smean, sinv;
    if (tid == 0) {
        float mean = rs[0] * (1.f / 16384.f);
        float var  = rs2[0] * (1.f / 16384.f) - mean * mean;
        smean = mean;
        sinv  = rsqrtf(var + 1e-5f);
    }
    __syncthreads();
    float mean = smean, inv = sinv;

    __shared__ u16 sh_h[16][258];
    __shared__ u16 sh_l[16][258];

#pragma unroll 1
    for (int chunk = 0; chunk < 4; chunk++) {
        int l0 = chunk * 256;
#pragma unroll 1
        for (int cc = 0; cc < 16; cc++) {
            int c = g * 16 + cc;
            float ga = gamma[c] * inv;
            float bt = beta[c] - mean * ga;
            float v = x[base + (size_t)cc * 1024 + l0 + tid];
            float y = v * ga + bt;
            u16 h, l;
            split1(y, h, l);
            sh_h[cc][tid] = h;
            sh_l[cc][tid] = l;
        }
        __syncthreads();
        int c = tid & 15, lq = tid >> 4;
#pragma unroll
        for (int step = 0; step < 16; step++) {
            int ll = step * 16 + lq;
            size_t o = ((size_t)b * 1024 + l0 + ll) * 512 + g * 16 + c;
            g_xnt_h[o] = sh_h[c][ll];
            g_xnt_l[o] = sh_l[c][ll];
        }
        __syncthreads();
    }
}

// ---------------------------------------------------------------------------
// Pipelined split-bf16 GEMM (2-stage cp.async ping-pong).  Race-free.
// V output (mode 2) now stored as f16 (feeds the f16 AV mma).
// ---------------------------------------------------------------------------
#define GST 24576   // stage stride in u16

__global__ void __launch_bounds__(256) gemm_mma(const float* __restrict__ bias0,
                                                const float* __restrict__ bias1,
                                                const float* __restrict__ bias2,
                                                const float* __restrict__ resid,
                                                float* __restrict__ extout,
                                                int qkv)
{
    extern __shared__ __align__(16) u16 dsm[];
    u32 sm = (u32)__cvta_generic_to_shared(dsm);

    int mode, mblk;
    const float* bias;
    if (qkv) {
        mode = blockIdx.y >> 2;
        mblk = blockIdx.y & 3;
        bias = (mode == 0) ? bias0 : (mode == 1) ? bias1 : bias2;
    } else {
        mode = 3;
        mblk = blockIdx.y;
        bias = bias0;
    }
    bool full3 = (mode < 2);

    int b  = blockIdx.z;
    int n0 = blockIdx.x * 64;
    int m0 = mblk * 128;
    const u16* Ah = g_wh + (size_t)mode * 262144;
    const u16* Al = g_wl + (size_t)mode * 262144;
    const u16* Bh = ((mode == 3) ? g_ah : g_xnt_h) + (size_t)b * 524288;
    const u16* Bl = ((mode == 3) ? g_al : g_xnt_l) + (size_t)b * 524288;

    int tid = threadIdx.x, wid = tid >> 5, lane = tid & 31;
    int wm = wid & 1, wn = wid >> 1;

    float acc[4][2][4] = {};

    int alr = lane & 15, ahalf = (lane >> 4) * 8;
    int bn = (lane >> 4) * 8 + (lane & 7);
    int bk = ((lane >> 3) & 1) * 8;

    auto load_stage = [&](int stage, int k0) {
        u32 sa_h = sm + (u32)(stage * GST) * 2;
        u32 sa_l = sa_h + 8192 * 2;
        u32 sb_h = sa_h + 16384 * 2;
        u32 sb_l = sa_h + 20480 * 2;
#pragma unroll
        for (int j = 0; j < 4; j++) {
            int idx = j * 256 + tid;
            int row = idx >> 3, ch = idx & 7;
            size_t off = (size_t)(m0 + row) * 512 + k0 + ch * 8;
            int so = swz(row, ch * 16);
            cp16(sa_h + so, Ah + off);
            cp16(sa_l + so, Al + off);
        }
#pragma unroll
        for (int j = 0; j < 2; j++) {
            int idx = j * 256 + tid;
            int row = idx >> 3, ch = idx & 7;
            size_t off = (size_t)(n0 + row) * 512 + k0 + ch * 8;
            int so = swz(row, ch * 16);
            cp16(sb_h + so, Bh + off);
            cp16(sb_l + so, Bl + off);
        }
        CP_COMMIT();
    };

    load_stage(0, 0);

#pragma unroll 1
    for (int it = 0; it < 8; it++) {
        if (it + 1 < 8) load_stage((it + 1) & 1, (it + 1) * 64);
        if (it + 1 < 8) { CP_WAIT(1); } else { CP_WAIT(0); }
        __syncthreads();

        u32 sa_h = sm + (u32)((it & 1) * GST) * 2;
        u32 sa_l = sa_h + 8192 * 2;
        u32 sb_h = sa_h + 16384 * 2;
        u32 sb_l = sa_h + 20480 * 2;

#pragma unroll
        for (int ks = 0; ks < 64; ks += 16) {
            u32 af[2][4][4], bf[2][4];
#pragma unroll
            for (int mt = 0; mt < 4; mt++) {
                int so = swz(wm * 64 + mt * 16 + alr, (ks + ahalf) * 2);
                ldsm4(af[0][mt], sa_h + so);
                ldsm4(af[1][mt], sa_l + so);
            }
            {
                int so = swz(wn * 16 + bn, (ks + bk) * 2);
                ldsm4(bf[0], sb_h + so);
                ldsm4(bf[1], sb_l + so);
            }
#pragma unroll
            for (int mt = 0; mt < 4; mt++)
#pragma unroll
                for (int nt = 0; nt < 2; nt++)
                    mma_bf16(acc[mt][nt], af[0][mt], &bf[0][nt * 2]);
#pragma unroll
            for (int mt = 0; mt < 4; mt++)
#pragma unroll
                for (int nt = 0; nt < 2; nt++)
                    mma_bf16(acc[mt][nt], af[0][mt], &bf[1][nt * 2]);
            if (full3) {
#pragma unroll
                for (int mt = 0; mt < 4; mt++)
#pragma unroll
                    for (int nt = 0; nt < 2; nt++)
                        mma_bf16(acc[mt][nt], af[1][mt], &bf[0][nt * 2]);
            }
        }
        __syncthreads();   // releases stage it&1 before next iter's load issue
    }

    // ---- epilogue ----
    const float scale = 0.35355339059327373f;
    int lr = lane >> 2, lc = (lane & 3) * 2;
#pragma unroll
    for (int mt = 0; mt < 4; mt++)
#pragma unroll
        for (int nt = 0; nt < 2; nt++) {
            int m = m0 + wm * 64 + mt * 16 + lr;
            int n = n0 + wn * 16 + nt * 8 + lc;
            float bi0 = bias[m], bi1 = bias[m + 8];
            float c0 = acc[mt][nt][0] + bi0, c1 = acc[mt][nt][1] + bi0;
            float c2 = acc[mt][nt][2] + bi1, c3 = acc[mt][nt][3] + bi1;
            if (mode == 3) {
                size_t o0 = ((size_t)b * 512 + m) * 1024 + n;
                size_t o1 = ((size_t)b * 512 + m + 8) * 1024 + n;
                float2 r0 = *(const float2*)&resid[o0];
                float2 r1 = *(const float2*)&resid[o1];
                *(float2*)&extout[o0] = make_float2(c0 + r0.x, c1 + r0.y);
                *(float2*)&extout[o1] = make_float2(c2 + r1.x, c3 + r1.y);
            } else if (mode == 2) {
                int bh = b * 8 + (m >> 6), d = m & 63;
                size_t o0 = ((size_t)bh * 64 + d) * 1024 + n;
                size_t o1 = ((size_t)bh * 64 + d + 8) * 1024 + n;
                *(u32*)&g_vh[o0] = pack_f16x2(c0, c1);   // f16 now
                *(u32*)&g_vh[o1] = pack_f16x2(c2, c3);
            } else {
                u16* dh = (mode == 0) ? g_qh : g_kh;
                u16* dl = (mode == 0) ? g_ql : g_kl;
                int bh = b * 8 + (m >> 6), d = m & 63;
                size_t base = (size_t)bh * 1024;
                u16 h, l;
                split1(c0 * scale, h, l);
                dh[(base + n) * 64 + d] = h;     dl[(base + n) * 64 + d] = l;
                split1(c1 * scale, h, l);
                dh[(base + n + 1) * 64 + d] = h; dl[(base + n + 1) * 64 + d] = l;
                split1(c2 * scale, h, l);
                dh[(base + n) * 64 + d + 8] = h;     dl[(base + n) * 64 + d + 8] = l;
                split1(c3 * scale, h, l);
                dh[(base + n + 1) * 64 + d + 8] = h; dl[(base + n + 1) * 64 + d + 8] = l;
            }
        }
}

// ---------------------------------------------------------------------------
// Attention, register-resident f16 P via packed ex2, race-free pipeline.
// S = QK^T: full 3-MMA bf16 split (feeds attn_map).
// P: s*log2e -> cvt.f16x2 -> ex2.approx.f16x2 (half the MUFU ops).
// AV = P(f16) x V(f16), 1 mma.f16 per tile.  lsum accumulated in f32 from
// unpacked f16 p values.
// smem (u16): q_h 0, q_l 8192, stage s at 16384+s*12288: {k_h, k_l +4096,
// v_h +8192}.  Total 40960 u16 = 80 KB.
// ---------------------------------------------------------------------------
__global__ void __launch_bounds__(256, 2) attn_mma(float* __restrict__ attn_out)
{
    extern __shared__ __align__(16) u16 dsm[];
    u32 sm = (u32)__cvta_generic_to_shared(dsm);
    u32 qs0 = sm, qs1 = sm + 8192 * 2;

    int bh = blockIdx.y, t0 = blockIdx.x * 128;
    int b = bh >> 3, head = bh & 7;
    int tid = threadIdx.x, wid = tid >> 5, lane = tid & 31;

    // ---- Q tile: 128 rows x 64 cols, both splits ----
#pragma unroll
    for (int j = 0; j < 4; j++) {
        int idx = j * 256 + tid;
        int row = idx >> 3, ch = idx & 7;
        size_t off = ((size_t)bh * 1024 + t0 + row) * 64 + ch * 8;
        int so = swz(row, ch * 16);
        cp16(qs0 + so, g_qh + off);
        cp16(qs1 + so, g_ql + off);
    }
    CP_COMMIT();

    auto load_kv = [&](int stage, int s0) {
        u32 kh = sm + (u32)(16384 + stage * 12288) * 2;
        u32 kl = kh + 4096 * 2;
        u32 vh = kh + 8192 * 2;
#pragma unroll
        for (int j = 0; j < 2; j++) {
            int idx = j * 256 + tid;
            int row = idx >> 3, ch = idx & 7;
            int so = swz(row, ch * 16);
            size_t ko = ((size_t)bh * 1024 + s0 + row) * 64 + ch * 8;
            cp16(kh + so, g_kh + ko);
            cp16(kl + so, g_kl + ko);
            size_t vo = ((size_t)bh * 64 + row) * 1024 + s0 + ch * 8;
            cp16(vh + so, g_vh + vo);
        }
        CP_COMMIT();
    };

    load_kv(0, 0);

    float avacc[8][4] = {};          // t16 x d64: 8 n8-tiles
    float lsum0 = 0.f, lsum1 = 0.f;  // row sums (rows lr, lr+8)
    const float l2e = 1.4426950408889634f;

    int alr = lane & 15, ahalf = (lane >> 4) * 8;
    int bn = (lane >> 4) * 8 + (lane & 7);
    int bkk = ((lane >> 3) & 1) * 8;
    int lr = lane >> 2, lc = (lane & 3) * 2;
    int trow = wid * 16;             // warp's t base within CTA

#pragma unroll 1
    for (int it = 0; it < 16; it++) {
        int s0 = it * 64;
        CP_WAIT(0);          // stage it&1 data arrived
        __syncthreads();     // every warp finished iter it-1 (released (it+1)&1)
        if (it + 1 < 16) load_kv((it + 1) & 1, s0 + 64);   // safe: buffer free

        u32 kh = sm + (u32)(16384 + (it & 1) * 12288) * 2;
        u32 kl = kh + 4096 * 2;
        u32 vh = kh + 8192 * 2;

        // ---- S = Q K^T : warp tile 16t x 64s, full 3-MMA split ----
        float sacc[8][4] = {};
#pragma unroll
        for (int kd = 0; kd < 64; kd += 16) {
            u32 afq0[4], afq1[4];
            {
                int so = swz(trow + alr, (kd + ahalf) * 2);
                ldsm4(afq0, qs0 + so);
                ldsm4(afq1, qs1 + so);
            }
#pragma unroll
            for (int g = 0; g < 4; g++) {
                u32 bk_h[4], bk_l[4];
                int so = swz(g * 16 + bn, (kd + bkk) * 2);
                ldsm4(bk_h, kh + so);
                ldsm4(bk_l, kl + so);
                mma_bf16(sacc[2*g],   afq0, &bk_h[0]);
                mma_bf16(sacc[2*g+1], afq0, &bk_h[2]);
                mma_bf16(sacc[2*g],   afq0, &bk_l[0]);
                mma_bf16(sacc[2*g+1], afq0, &bk_l[2]);
                mma_bf16(sacc[2*g],   afq1, &bk_h[0]);
                mma_bf16(sacc[2*g+1], afq1, &bk_h[2]);
            }
        }

        // ---- dump raw scores; p = exp2(s*log2e) via packed f16 ex2 ----
        u32 pr0[8], pr1[8];   // f16x2 pairs
        {
            size_t base = (size_t)bh * 1048576 + (size_t)(t0 + trow + lr) * 1024 + s0 + lc;
#pragma unroll
            for (int nt = 0; nt < 8; nt++) {
                __stcs((float2*)&attn_out[base + nt * 8],
                       make_float2(sacc[nt][0], sacc[nt][1]));
                __stcs((float2*)&attn_out[base + 8192 + nt * 8],
                       make_float2(sacc[nt][2], sacc[nt][3]));
                u32 e01 = pack_f16x2(sacc[nt][0] * l2e, sacc[nt][1] * l2e);
                u32 e23 = pack_f16x2(sacc[nt][2] * l2e, sacc[nt][3] * l2e);
                u32 p01 = ex2_f16x2(e01);
                u32 p23 = ex2_f16x2(e23);
                pr0[nt] = p01;
                pr1[nt] = p23;
                float2 f01 = __half22float2(*reinterpret_cast<__half2*>(&p01));
                float2 f23 = __half22float2(*reinterpret_cast<__half2*>(&p23));
                lsum0 += f01.x + f01.y;
                lsum1 += f23.x + f23.y;
            }
        }

        // ---- AV: out(t,d) += P(t,s) * V(d,s)^T, f16 x f16 ----
#pragma unroll
        for (int c = 0; c < 4; c++) {
            u32 aP[4] = { pr0[2*c], pr1[2*c], pr0[2*c + 1], pr1[2*c + 1] };
#pragma unroll
            for (int g = 0; g < 4; g++) {
                u32 bv[4];
                int so = swz(g * 16 + bn, (c * 16 + bkk) * 2);
                ldsm4(bv, vh + so);
                mma_f16(avacc[2*g],   aP, &bv[0]);
                mma_f16(avacc[2*g+1], aP, &bv[2]);
            }
        }
    }

    // ---- row sums within quad, normalize, store a (split bf16) ----
    lsum0 += __shfl_xor_sync(0xffffffffu, lsum0, 1);
    lsum0 += __shfl_xor_sync(0xffffffffu, lsum0, 2);
    lsum1 += __shfl_xor_sync(0xffffffffu, lsum1, 1);
    lsum1 += __shfl_xor_sync(0xffffffffu, lsum1, 2);
    float inv0 = 1.f / lsum0;
    float inv1 = 1.f / lsum1;

#pragma unroll
    for (int dt = 0; dt < 8; dt++) {
        int dcol = head * 64 + dt * 8 + lc;
        u32 h0, l0, h1, l1;
        cvt_pair(avacc[dt][0] * inv0, avacc[dt][1] * inv0, h0, l0);
        cvt_pair(avacc[dt][2] * inv1, avacc[dt][3] * inv1, h1, l1);
        size_t o0 = ((size_t)b * 1024 + t0 + trow + lr) * 512 + dcol;
        size_t o1 = ((size_t)b * 1024 + t0 + trow + lr + 8) * 512 + dcol;
        *(u32*)&g_ah[o0] = h0; *(u32*)&g_al[o0] = l0;
        *(u32*)&g_ah[o1] = h1; *(u32*)&g_al[o1] = l1;
    }
}

// ---------------------------------------------------------------------------
extern "C" void kernel_launch(void* const* d_in, const int* in_sizes, int n_in,
                              void* d_out, int out_size)
{
    const float* x     = (const float*)d_in[0];
    const float* gamma = (const float*)d_in[2];
    const float* beta  = (const float*)d_in[3];
    const float* Wq    = (const float*)d_in[4];
    const float* bq    = (const float*)d_in[5];
    const float* Wk    = (const float*)d_in[6];
    const float* bk    = (const float*)d_in[7];
    const float* Wv    = (const float*)d_in[8];
    const float* bv    = (const float*)d_in[9];
    const float* Wo    = (const float*)d_in[10];
    const float* bo    = (const float*)d_in[11];

    float* out = (float*)d_out;
    float* attn_out;
    if ((long long)out_size >= (long long)BCL + (long long)ATT) {
        attn_out = out + (size_t)BCL;
    } else {
        float* sink;
        cudaGetSymbolAddress((void**)&sink, g_attn_sink);
        attn_out = sink;
    }

    const int GEMM_SMEM = 96 * 1024;
    const int ATTN_SMEM = 80 * 1024;
    cudaFuncSetAttribute(gemm_mma, cudaFuncAttributeMaxDynamicSharedMemorySize, GEMM_SMEM);
    cudaFuncSetAttribute(attn_mma, cudaFuncAttributeMaxDynamicSharedMemorySize, ATTN_SMEM);

    prep_kernel<<<1280, 256>>>(x, gamma, beta, Wq, Wk, Wv, Wo);

    // fused QKV projections
    gemm_mma<<<dim3(16, 12, B_), 256, GEMM_SMEM>>>(bq, bk, bv, nullptr, nullptr, 1);

    attn_mma<<<dim3(8, 64), 256, ATTN_SMEM>>>(attn_out);

    gemm_mma<<<dim3(16, 4, B_), 256, GEMM_SMEM>>>(bo, nullptr, nullptr, x, out, 0);
}